// round 13
// baseline (speedup 1.0000x reference)
#include <cuda_runtime.h>
#include <cuda_fp16.h>
#include <cstdint>
#include <cstddef>

#define IN_F   4096
#define OUT_F  4096
#define MTOT   8192   // 4 * 2048

// ---------------- scratch (static device globals: allocation-free) -----------
// Tile-major, pre-swizzled layouts (exactly what the GEMM wants in smem):
// g_Xh: [mtile128(64)][kchunk(64)] blocks of 16384B = 128 rows x 128B (swizzled)
// g_Wh: [ntile256(16)][kchunk(64)] blocks of 32768B = 256 rows x 128B (swizzled)
__device__ __half g_Xh[(size_t)MTOT * IN_F];   // 64 MiB
__device__ __half g_Wh[(size_t)OUT_F * IN_F];  // 32 MiB
__device__ int g_cntX[64];
__device__ int g_cntW[16];
__device__ int g_tile;

// ---------------- PTX helpers ----------------
__device__ __forceinline__ uint32_t smem_u32(const void* p) {
    uint32_t r;
    asm("{ .reg .u64 t; cvta.to.shared.u64 t, %1; cvt.u32.u64 %0, t; }"
        : "=r"(r) : "l"(p));
    return r;
}
__device__ __forceinline__ void ldsm_x4(uint32_t* r, uint32_t addr) {
    asm volatile("ldmatrix.sync.aligned.m8n8.x4.shared.b16 {%0,%1,%2,%3}, [%4];"
                 : "=r"(r[0]), "=r"(r[1]), "=r"(r[2]), "=r"(r[3]) : "r"(addr));
}
__device__ __forceinline__ void mma16816(float* c, const uint32_t* a, const uint32_t* b) {
    asm volatile(
        "mma.sync.aligned.m16n8k16.row.col.f32.f16.f16.f32 "
        "{%0,%1,%2,%3}, {%4,%5,%6,%7}, {%8,%9}, {%0,%1,%2,%3};"
        : "+f"(c[0]), "+f"(c[1]), "+f"(c[2]), "+f"(c[3])
        : "r"(a[0]), "r"(a[1]), "r"(a[2]), "r"(a[3]), "r"(b[0]), "r"(b[1]));
}
__device__ __forceinline__ void bulk_g2s(uint32_t dst, const void* src, uint32_t bytes,
                                         uint32_t mbar) {
    asm volatile(
        "cp.async.bulk.shared::cta.global.mbarrier::complete_tx::bytes [%0], [%1], %2, [%3];"
        :: "r"(dst), "l"(src), "r"(bytes), "r"(mbar) : "memory");
}
__device__ __forceinline__ int ld_acq(const int* p) {
    int v;
    asm volatile("ld.acquire.gpu.s32 %0, [%1];" : "=r"(v) : "l"(p) : "memory");
    return v;
}
#define MBARRIER_INIT(addr, cnt) \
    asm volatile("mbarrier.init.shared.b64 [%0], %1;" :: "r"((uint32_t)(addr)), "r"((uint32_t)(cnt)) : "memory")
#define MBARRIER_EXPECT_TX(addr, bytes) \
    asm volatile("mbarrier.arrive.expect_tx.shared.b64 _, [%0], %1;" :: "r"((uint32_t)(addr)), "r"((uint32_t)(bytes)) : "memory")
#define MBARRIER_ARRIVE(addr) \
    asm volatile("mbarrier.arrive.release.cta.shared::cta.b64 _, [%0];" :: "r"((uint32_t)(addr)) : "memory")
#define MBARRIER_WAIT_PARITY(mbar_smem_addr, phase_parity) do {                         \
    uint32_t _mbar = (uint32_t)(mbar_smem_addr);                                        \
    uint32_t _parity = (uint32_t)(phase_parity);                                        \
    uint32_t _done;                                                                     \
    asm volatile("{\n\t.reg .pred p;\n\t"                                               \
        "mbarrier.try_wait.parity.acquire.cta.shared::cta.b64 p, [%1], %2;\n\t"         \
        "selp.b32 %0, 1, 0, p;\n\t}"                                                    \
        : "=r"(_done) : "r"(_mbar), "r"(_parity) : "memory");                           \
    if (!_done) {                                                                       \
        asm volatile("{\n\t.reg .pred P1;\n\t"                                          \
            "WAIT_LOOP_%=:\n\t"                                                         \
            "mbarrier.try_wait.parity.acquire.cta.shared::cta.b64 P1, [%0], %1, 0x989680;\n\t" \
            "@P1 bra.uni WAIT_DONE_%=;\n\t"                                             \
            "bra.uni WAIT_LOOP_%=;\n\t"                                                 \
            "WAIT_DONE_%=:\n\t}"                                                        \
            :: "r"(_mbar), "r"(_parity) : "memory");                                    \
    }                                                                                   \
} while (0)

// ---------------- config ----------------
#define TO 32
#define TI 512
#define N_FOLD_UNITS 1024          // (32 rows x 512 cols) each
#define N_CONV_UNITS 2048          // 4 x-rows each
#define N_UNITS (N_FOLD_UNITS + N_CONV_UNITS)
#define NSTG 128                   // staging blocks (low ids, scheduled first)
#define GRID_BLOCKS 296            // <= 2 * 148 SMs (all resident)

#define BM 128
#define BN 128
#define BK 64
#define NST 3
#define A_SZ (BM * 128)                   // 16384
#define B_SZ (BN * 128)                   // 16384
#define ST_SZ (A_SZ + B_SZ)               // 32768
#define SMEM_T0 1024
#define FUSED_SMEM (SMEM_T0 + NST * ST_SZ) // 99328
#define KCH (IN_F / BK)                   // 64
#define NTILES ((MTOT / BM) * (OUT_F / BN))   // 64 * 32 = 2048
#define FULL_BAR(sb, s)  ((sb) + 8 * (s))
#define EMPTY_BAR(sb, s) ((sb) + 24 + 8 * (s))

// ---------------- init kernel: zero scheduler state -------------------------
__global__ void k_init() {
    int t = threadIdx.x;
    if (t < 64) g_cntX[t] = 0;
    if (t < 16) g_cntW[t] = 0;
    if (t == 0) g_tile = 0;
}

// ---------------- staging units (device functions) ---------------------------
__device__ void conv_unit(int v, int tid, const float4* __restrict__ x) {
    // rows 4v .. 4v+3 of x -> g_Xh tile-major swizzled
    for (int i = tid; i < 4 * 512; i += 256) {
        int row = 4 * v + (i >> 9);
        int kg = i & 511;
        int g = row * 512 + kg;
        float4 v0 = x[g * 2], v1 = x[g * 2 + 1];
        __half2 h0 = __floats2half2_rn(v0.x, v0.y);
        __half2 h1 = __floats2half2_rn(v0.z, v0.w);
        __half2 h2 = __floats2half2_rn(v1.x, v1.y);
        __half2 h3 = __floats2half2_rn(v1.z, v1.w);
        uint4 o;
        o.x = *reinterpret_cast<uint32_t*>(&h0);
        o.y = *reinterpret_cast<uint32_t*>(&h1);
        o.z = *reinterpret_cast<uint32_t*>(&h2);
        o.w = *reinterpret_cast<uint32_t*>(&h3);
        int kchunk = kg >> 3, chunk = kg & 7;
        int r = row & 127, mtile = row >> 7;
        size_t off = ((size_t)(mtile * 64 + kchunk) << 14)
                   + (uint32_t)(r * 128 + (((chunk ^ (r & 7)) & 7) << 4));
        *reinterpret_cast<uint4*>(reinterpret_cast<char*>(g_Xh) + off) = o;
    }
}

__device__ void fold_unit(int u, int tid, char* smem,
                          const int* __restrict__ qw, const float* __restrict__ qs,
                          const float* __restrict__ A, const float* __restrict__ B) {
    float (*As)[TI + 4] = (float (*)[TI + 4])(smem + SMEM_T0);
    float (*Bs)[16]     = (float (*)[16])(smem + SMEM_T0 + 16 * (TI + 4) * 4);
    float* Ss           = (float*)(smem + SMEM_T0 + 16 * (TI + 4) * 4 + TO * 16 * 4);
    const int ob = u >> 3;               // row strip 0..127
    const int cb = (u & 7) * TI;         // col strip base
    const int o0 = ob * TO;
    for (int t = tid; t < TO * 16; t += 256)
        Bs[t / 16][t % 16] = B[(size_t)(o0 + t / 16) * 16 + (t % 16)];
    if (tid < TO) Ss[tid] = qs[o0 + tid];
    for (int t = tid; t < 16 * (TI / 4); t += 256) {
        int r = t / (TI / 4), j = t % (TI / 4);
        float4 v = reinterpret_cast<const float4*>(A + (size_t)r * IN_F + cb)[j];
        *reinterpret_cast<float4*>(&As[r][j * 4]) = v;
    }
    __syncthreads();
    const int ro = tid >> 3;    // 0..31
    const int l8 = tid & 7;     // 0..7
    const int o = o0 + ro;
    const int ntile = o >> 8, rr = o & 255;
    const float s = Ss[ro];
    const float* brow = Bs[ro];
    #pragma unroll 4
    for (int j = 0; j < TI / 32; ++j) {
        int il = l8 * 4 + j * 32;
        int4 q4 = *reinterpret_cast<const int4*>(&qw[(size_t)o * IN_F + cb + il]);
        float a0 = q4.x * s, a1 = q4.y * s, a2 = q4.z * s, a3 = q4.w * s;
        #pragma unroll
        for (int r = 0; r < 16; ++r) {
            float b2 = 2.0f * brow[r];
            a0 = fmaf(b2, As[r][il + 0], a0);
            a1 = fmaf(b2, As[r][il + 1], a1);
            a2 = fmaf(b2, As[r][il + 2], a2);
            a3 = fmaf(b2, As[r][il + 3], a3);
        }
        __half2 h0 = __floats2half2_rn(a0, a1);
        __half2 h1 = __floats2half2_rn(a2, a3);
        uint2 w;
        w.x = *reinterpret_cast<uint32_t*>(&h0);
        w.y = *reinterpret_cast<uint32_t*>(&h1);
        int col = cb + il;
        int kchunk = col >> 6;
        int c6 = col & 63;
        int chunk = c6 >> 3, within = c6 & 7;
        size_t off = ((size_t)(ntile * 64 + kchunk) << 15)
                   + (uint32_t)(rr * 128 + (((chunk ^ (rr & 7)) & 7) << 4) + within * 2);
        *reinterpret_cast<uint2*>(reinterpret_cast<char*>(g_Wh) + off) = w;
    }
}

// ---------------- fused persistent kernel ------------------------------------
__global__ void __launch_bounds__(256, 2)
k_fused(const float4* __restrict__ x,
        const int* __restrict__ qw, const float* __restrict__ qs,
        const float* __restrict__ A, const float* __restrict__ B,
        const float* __restrict__ bias, float* __restrict__ out) {
    extern __shared__ char smem[];
    uint32_t sb = smem_u32(smem);
    const int tid = threadIdx.x;
    const int bid = blockIdx.x;
    const int wid = tid >> 5, lid = tid & 31;
    const int wm = wid & 1;
    const int wn = wid >> 1;

    // ---------------- phase 1: staging (blocks 0..NSTG-1) ----------------
    if (bid < NSTG) {
        for (int u = bid; u < N_UNITS; u += NSTG) {
            if (u < N_FOLD_UNITS) fold_unit(u, tid, smem, qw, qs, A, B);
            else                  conv_unit(u - N_FOLD_UNITS, tid, x);
            __threadfence();
            __syncthreads();
            if (tid == 0) {
                if (u < N_FOLD_UNITS) atomicAdd(&g_cntW[u >> 6], 1);
                else                  atomicAdd(&g_cntX[(u - N_FOLD_UNITS) >> 5], 1);
            }
            __syncthreads();
        }
    }

    // ---------------- phase 2: persistent GEMM tile loop ----------------
    volatile int* sm_t = (volatile int*)(smem + 64);
    for (;;) {
        if (tid == 0) *sm_t = atomicAdd(&g_tile, 1);
        __syncthreads();          // broadcast t; also separates prior tile's barrier ops
        int t = *sm_t;
        if (t >= NTILES) break;
        const int mtile = t >> 5;        // 0..63  (mtile-major: early tiles ready first)
        const int ntile = t & 31;        // 0..31
        const char* gA = reinterpret_cast<const char*>(g_Xh) + ((size_t)mtile * 64 << 14);
        const char* gB = reinterpret_cast<const char*>(g_Wh)
                       + ((size_t)(ntile >> 1) * 64 << 15) + (size_t)(ntile & 1) * 16384;

        if (tid == 0) {
            // wait for staging of this tile's inputs
            while (ld_acq(&g_cntX[mtile]) < 32)      __nanosleep(128);
            while (ld_acq(&g_cntW[ntile >> 1]) < 64) __nanosleep(128);
            // re-init barriers (idle at tile boundary); resets phase to 0
            #pragma unroll
            for (int s = 0; s < NST; ++s) {
                MBARRIER_INIT(FULL_BAR(sb, s), 1);
                MBARRIER_INIT(EMPTY_BAR(sb, s), 8);
            }
        }
        __syncthreads();          // init visible to all warps before try_wait

        if (tid == 0) {
            #pragma unroll
            for (int c = 0; c < NST; ++c) {
                uint32_t stg = sb + SMEM_T0 + c * ST_SZ;
                MBARRIER_EXPECT_TX(FULL_BAR(sb, c), ST_SZ);
                bulk_g2s(stg,        gA + ((size_t)c << 14), A_SZ, FULL_BAR(sb, c));
                bulk_g2s(stg + A_SZ, gB + ((size_t)c << 15), B_SZ, FULL_BAR(sb, c));
            }
        }

        float ac[4][4][4];
        #pragma unroll
        for (int i = 0; i < 4; ++i)
            #pragma unroll
            for (int j = 0; j < 4; ++j)
                #pragma unroll
                for (int k = 0; k < 4; ++k) ac[i][j][k] = 0.0f;

        int s = 0, q = 0;
        for (int c = 0; c < KCH; ++c) {
            MBARRIER_WAIT_PARITY(FULL_BAR(sb, s), (uint32_t)(q & 1));

            uint32_t Ab = sb + SMEM_T0 + s * ST_SZ;
            uint32_t Bb = Ab + A_SZ;
            #pragma unroll
            for (int ks = 0; ks < BK / 16; ++ks) {
                uint32_t af[16], bf[8];
                #pragma unroll
                for (int i = 0; i < 4; ++i) {
                    int row = wm * 64 + i * 16 + (lid & 15);
                    int chunk = ks * 2 + (lid >> 4);
                    uint32_t addr = Ab + (uint32_t)(row * 128) + (((chunk ^ (row & 7)) & 7) << 4);
                    ldsm_x4(af + i * 4, addr);
                }
                #pragma unroll
                for (int j = 0; j < 2; ++j) {
                    int row = wn * 32 + j * 16 + ((lid >> 4) << 3) + (lid & 7);
                    int chunk = ks * 2 + ((lid >> 3) & 1);
                    uint32_t addr = Bb + (uint32_t)(row * 128) + (((chunk ^ (row & 7)) & 7) << 4);
                    ldsm_x4(bf + j * 4, addr);
                }
                #pragma unroll
                for (int i = 0; i < 4; ++i) {
                    #pragma unroll
                    for (int jj = 0; jj < 4; ++jj) {
                        mma16816(ac[i][jj], &af[i * 4], &bf[(jj >> 1) * 4 + (jj & 1) * 2]);
                    }
                }
            }

            if (lid == 0) MBARRIER_ARRIVE(EMPTY_BAR(sb, s));

            if (tid == 0 && c + NST < KCH) {
                MBARRIER_WAIT_PARITY(EMPTY_BAR(sb, s), (uint32_t)(q & 1));
                int nc = c + NST;
                uint32_t stg = sb + SMEM_T0 + s * ST_SZ;
                MBARRIER_EXPECT_TX(FULL_BAR(sb, s), ST_SZ);
                bulk_g2s(stg,        gA + ((size_t)nc << 14), A_SZ, FULL_BAR(sb, s));
                bulk_g2s(stg + A_SZ, gB + ((size_t)nc << 15), B_SZ, FULL_BAR(sb, s));
            }
            ++s; if (s == NST) { s = 0; ++q; }
        }

        // epilogue: write 64x32 warp tile with bias
        const int m0 = mtile * BM, n0 = ntile * BN;
        const int mbase = m0 + wm * 64 + (lid >> 2);
        const int nbase = n0 + wn * 32 + (lid & 3) * 2;
        #pragma unroll
        for (int jj = 0; jj < 4; ++jj) {
            int n = nbase + jj * 8;
            float b0 = bias[n], b1 = bias[n + 1];
            #pragma unroll
            for (int i = 0; i < 4; ++i) {
                int m = mbase + i * 16;
                float2 v0 = make_float2(ac[i][jj][0] + b0, ac[i][jj][1] + b1);
                float2 v1 = make_float2(ac[i][jj][2] + b0, ac[i][jj][3] + b1);
                *reinterpret_cast<float2*>(&out[(size_t)m * OUT_F + n]) = v0;
                *reinterpret_cast<float2*>(&out[(size_t)(m + 8) * OUT_F + n]) = v1;
            }
        }
    }
}

// ---------------- launcher ----------------
extern "C" void kernel_launch(void* const* d_in, const int* in_sizes, int n_in,
                              void* d_out, int out_size) {
    const float* x    = (const float*)d_in[0];
    const int*   qw   = (const int*)  d_in[1];
    const float* qs   = (const float*)d_in[2];
    const float* bias = (const float*)d_in[3];
    const float* lA   = (const float*)d_in[4];
    const float* lB   = (const float*)d_in[5];
    float* out = (float*)d_out;

    cudaFuncSetAttribute(k_fused, cudaFuncAttributeMaxDynamicSharedMemorySize, FUSED_SMEM);

    k_init<<<1, 128>>>();
    k_fused<<<GRID_BLOCKS, 256, FUSED_SMEM>>>(reinterpret_cast<const float4*>(x),
                                              qw, qs, lA, lB, bias, out);
}

// round 14
// speedup vs baseline: 1.0465x; 1.0465x over previous
#include <cuda_runtime.h>
#include <cuda_fp16.h>
#include <cstdint>
#include <cstddef>

#define IN_F   4096
#define OUT_F  4096
#define MTOT   8192   // 4 * 2048

// ---------------- scratch (static device globals: allocation-free) -----------
__device__ __half g_Xh[(size_t)MTOT * IN_F];   // 64 MiB, tile-major swizzled
__device__ __half g_Wh[(size_t)OUT_F * IN_F];  // 32 MiB, tile-major swizzled
__device__ int g_cntX[64];
__device__ int g_cntW[16];
__device__ int g_tile;

// ---------------- PTX helpers ----------------
__device__ __forceinline__ uint32_t smem_u32(const void* p) {
    uint32_t r;
    asm("{ .reg .u64 t; cvta.to.shared.u64 t, %1; cvt.u32.u64 %0, t; }"
        : "=r"(r) : "l"(p));
    return r;
}
__device__ __forceinline__ void ldsm_x4(uint32_t* r, uint32_t addr) {
    asm volatile("ldmatrix.sync.aligned.m8n8.x4.shared.b16 {%0,%1,%2,%3}, [%4];"
                 : "=r"(r[0]), "=r"(r[1]), "=r"(r[2]), "=r"(r[3]) : "r"(addr));
}
__device__ __forceinline__ void mma16816(float* c, const uint32_t* a, const uint32_t* b) {
    asm volatile(
        "mma.sync.aligned.m16n8k16.row.col.f32.f16.f16.f32 "
        "{%0,%1,%2,%3}, {%4,%5,%6,%7}, {%8,%9}, {%0,%1,%2,%3};"
        : "+f"(c[0]), "+f"(c[1]), "+f"(c[2]), "+f"(c[3])
        : "r"(a[0]), "r"(a[1]), "r"(a[2]), "r"(a[3]), "r"(b[0]), "r"(b[1]));
}
__device__ __forceinline__ void bulk_g2s(uint32_t dst, const void* src, uint32_t bytes,
                                         uint32_t mbar) {
    asm volatile(
        "cp.async.bulk.shared::cta.global.mbarrier::complete_tx::bytes [%0], [%1], %2, [%3];"
        :: "r"(dst), "l"(src), "r"(bytes), "r"(mbar) : "memory");
}
__device__ __forceinline__ int ld_acq(const int* p) {
    int v;
    asm volatile("ld.acquire.gpu.s32 %0, [%1];" : "=r"(v) : "l"(p) : "memory");
    return v;
}
#define MBARRIER_INIT(addr, cnt) \
    asm volatile("mbarrier.init.shared.b64 [%0], %1;" :: "r"((uint32_t)(addr)), "r"((uint32_t)(cnt)) : "memory")
#define MBARRIER_EXPECT_TX(addr, bytes) \
    asm volatile("mbarrier.arrive.expect_tx.shared.b64 _, [%0], %1;" :: "r"((uint32_t)(addr)), "r"((uint32_t)(bytes)) : "memory")
#define MBARRIER_ARRIVE(addr) \
    asm volatile("mbarrier.arrive.release.cta.shared::cta.b64 _, [%0];" :: "r"((uint32_t)(addr)) : "memory")
#define MBARRIER_WAIT_PARITY(mbar_smem_addr, phase_parity) do {                         \
    uint32_t _mbar = (uint32_t)(mbar_smem_addr);                                        \
    uint32_t _parity = (uint32_t)(phase_parity);                                        \
    uint32_t _done;                                                                     \
    asm volatile("{\n\t.reg .pred p;\n\t"                                               \
        "mbarrier.try_wait.parity.acquire.cta.shared::cta.b64 p, [%1], %2;\n\t"         \
        "selp.b32 %0, 1, 0, p;\n\t}"                                                    \
        : "=r"(_done) : "r"(_mbar), "r"(_parity) : "memory");                           \
    if (!_done) {                                                                       \
        asm volatile("{\n\t.reg .pred P1;\n\t"                                          \
            "WAIT_LOOP_%=:\n\t"                                                         \
            "mbarrier.try_wait.parity.acquire.cta.shared::cta.b64 P1, [%0], %1, 0x989680;\n\t" \
            "@P1 bra.uni WAIT_DONE_%=;\n\t"                                             \
            "bra.uni WAIT_LOOP_%=;\n\t"                                                 \
            "WAIT_DONE_%=:\n\t}"                                                        \
            :: "r"(_mbar), "r"(_parity) : "memory");                                    \
    }                                                                                   \
} while (0)

// ---------------- config ----------------
#define TO 32
#define TI 512
#define N_FOLD_UNITS 1024          // (32 rows x 512 cols) each
#define N_CONV_UNITS 2048          // 4 x-rows each, mtile-ordered
#define NSTG 128                   // conv blocks (low ids)
#define GRID_BLOCKS 296            // <= 2 * 148 SMs (all resident)

#define BM 128
#define BN 128
#define BK 64
#define NST 3
#define A_SZ (BM * 128)                   // 16384
#define B_SZ (BN * 128)                   // 16384
#define ST_SZ (A_SZ + B_SZ)               // 32768
#define SMEM_T0 1024
#define FUSED_SMEM (SMEM_T0 + NST * ST_SZ) // 99328
#define KCH (IN_F / BK)                   // 64
#define NTILES ((MTOT / BM) * (OUT_F / BN))   // 2048
#define FULL_BAR(sb, s)  ((sb) + 8 * (s))
#define EMPTY_BAR(sb, s) ((sb) + 24 + 8 * (s))

// ---------------- init kernel: zero scheduler state -------------------------
__global__ void k_init() {
    int t = threadIdx.x;
    if (t < 64) g_cntX[t] = 0;
    if (t < 16) g_cntW[t] = 0;
    if (t == 0) g_tile = 0;
}

// ---------------- staging units ----------------------------------------------
__device__ void conv_unit(int v, int tid, const float4* __restrict__ x) {
    // rows 4v .. 4v+3 of x -> g_Xh tile-major swizzled
    for (int i = tid; i < 4 * 512; i += 256) {
        int row = 4 * v + (i >> 9);
        int kg = i & 511;
        int g = row * 512 + kg;
        float4 v0 = x[g * 2], v1 = x[g * 2 + 1];
        __half2 h0 = __floats2half2_rn(v0.x, v0.y);
        __half2 h1 = __floats2half2_rn(v0.z, v0.w);
        __half2 h2 = __floats2half2_rn(v1.x, v1.y);
        __half2 h3 = __floats2half2_rn(v1.z, v1.w);
        uint4 o;
        o.x = *reinterpret_cast<uint32_t*>(&h0);
        o.y = *reinterpret_cast<uint32_t*>(&h1);
        o.z = *reinterpret_cast<uint32_t*>(&h2);
        o.w = *reinterpret_cast<uint32_t*>(&h3);
        int kchunk = kg >> 3, chunk = kg & 7;
        int r = row & 127, mtile = row >> 7;
        size_t off = ((size_t)(mtile * 64 + kchunk) << 14)
                   + (uint32_t)(r * 128 + (((chunk ^ (r & 7)) & 7) << 4));
        *reinterpret_cast<uint4*>(reinterpret_cast<char*>(g_Xh) + off) = o;
    }
}

__device__ void fold_unit(int u, int tid, char* smem,
                          const int* __restrict__ qw, const float* __restrict__ qs,
                          const float* __restrict__ A, const float* __restrict__ B) {
    float (*As)[TI + 4] = (float (*)[TI + 4])(smem + SMEM_T0);
    float (*Bs)[16]     = (float (*)[16])(smem + SMEM_T0 + 16 * (TI + 4) * 4);
    float* Ss           = (float*)(smem + SMEM_T0 + 16 * (TI + 4) * 4 + TO * 16 * 4);
    const int ob = u >> 3;               // row strip 0..127
    const int cb = (u & 7) * TI;         // col strip base
    const int o0 = ob * TO;
    for (int t = tid; t < TO * 16; t += 256)
        Bs[t / 16][t % 16] = B[(size_t)(o0 + t / 16) * 16 + (t % 16)];
    if (tid < TO) Ss[tid] = qs[o0 + tid];
    for (int t = tid; t < 16 * (TI / 4); t += 256) {
        int r = t / (TI / 4), j = t % (TI / 4);
        float4 v = reinterpret_cast<const float4*>(A + (size_t)r * IN_F + cb)[j];
        *reinterpret_cast<float4*>(&As[r][j * 4]) = v;
    }
    __syncthreads();
    const int ro = tid >> 3;    // 0..31
    const int l8 = tid & 7;     // 0..7
    const int o = o0 + ro;
    const int ntile = o >> 8, rr = o & 255;
    const float s = Ss[ro];
    const float* brow = Bs[ro];
    #pragma unroll 4
    for (int j = 0; j < TI / 32; ++j) {
        int il = l8 * 4 + j * 32;
        int4 q4 = *reinterpret_cast<const int4*>(&qw[(size_t)o * IN_F + cb + il]);
        float a0 = q4.x * s, a1 = q4.y * s, a2 = q4.z * s, a3 = q4.w * s;
        #pragma unroll
        for (int r = 0; r < 16; ++r) {
            float b2 = 2.0f * brow[r];
            a0 = fmaf(b2, As[r][il + 0], a0);
            a1 = fmaf(b2, As[r][il + 1], a1);
            a2 = fmaf(b2, As[r][il + 2], a2);
            a3 = fmaf(b2, As[r][il + 3], a3);
        }
        __half2 h0 = __floats2half2_rn(a0, a1);
        __half2 h1 = __floats2half2_rn(a2, a3);
        uint2 w;
        w.x = *reinterpret_cast<uint32_t*>(&h0);
        w.y = *reinterpret_cast<uint32_t*>(&h1);
        int col = cb + il;
        int kchunk = col >> 6;
        int c6 = col & 63;
        int chunk = c6 >> 3, within = c6 & 7;
        size_t off = ((size_t)(ntile * 64 + kchunk) << 15)
                   + (uint32_t)(rr * 128 + (((chunk ^ (rr & 7)) & 7) << 4) + within * 2);
        *reinterpret_cast<uint2*>(reinterpret_cast<char*>(g_Wh) + off) = w;
    }
}

// ---------------- fused persistent kernel ------------------------------------
__global__ void __launch_bounds__(256, 2)
k_fused(const float4* __restrict__ x,
        const int* __restrict__ qw, const float* __restrict__ qs,
        const float* __restrict__ A, const float* __restrict__ B,
        const float* __restrict__ bias, float* __restrict__ out) {
    extern __shared__ char smem[];
    uint32_t sb = smem_u32(smem);
    const int tid = threadIdx.x;
    const int bid = blockIdx.x;
    const int wid = tid >> 5, lid = tid & 31;
    const int wm = wid & 1;
    const int wn = wid >> 1;

    // -------- phase A: fold W on ALL blocks (fast, full-width) --------
    for (int u = bid; u < N_FOLD_UNITS; u += GRID_BLOCKS) {
        fold_unit(u, tid, smem, qw, qs, A, B);
        __threadfence();
        __syncthreads();
        if (tid == 0) atomicAdd(&g_cntW[u >> 6], 1);
        __syncthreads();
    }

    // -------- phase B: conv x on blocks 0..NSTG-1, mtile order --------
    if (bid < NSTG) {
        for (int v = bid; v < N_CONV_UNITS; v += NSTG) {
            conv_unit(v, tid, x);
            __threadfence();
            __syncthreads();
            if (tid == 0) atomicAdd(&g_cntX[v >> 5], 1);
            __syncthreads();
        }
    }

    // -------- phase C: persistent GEMM tile loop --------
    volatile int* sm_t = (volatile int*)(smem + 64);
    for (;;) {
        if (tid == 0) *sm_t = atomicAdd(&g_tile, 1);
        __syncthreads();
        int t = *sm_t;
        if (t >= NTILES) break;
        const int mtile = t >> 5;        // mtile-major: matches conv production order
        const int ntile = t & 31;
        const char* gA = reinterpret_cast<const char*>(g_Xh) + ((size_t)mtile * 64 << 14);
        const char* gB = reinterpret_cast<const char*>(g_Wh)
                       + ((size_t)(ntile >> 1) * 64 << 15) + (size_t)(ntile & 1) * 16384;

        if (tid == 0) {
            while (ld_acq(&g_cntW[ntile >> 1]) < 64) __nanosleep(256);
            while (ld_acq(&g_cntX[mtile]) < 32)      __nanosleep(256);
            #pragma unroll
            for (int s = 0; s < NST; ++s) {
                MBARRIER_INIT(FULL_BAR(sb, s), 1);
                MBARRIER_INIT(EMPTY_BAR(sb, s), 8);
            }
        }
        __syncthreads();

        if (tid == 0) {
            #pragma unroll
            for (int c = 0; c < NST; ++c) {
                uint32_t stg = sb + SMEM_T0 + c * ST_SZ;
                MBARRIER_EXPECT_TX(FULL_BAR(sb, c), ST_SZ);
                bulk_g2s(stg,        gA + ((size_t)c << 14), A_SZ, FULL_BAR(sb, c));
                bulk_g2s(stg + A_SZ, gB + ((size_t)c << 15), B_SZ, FULL_BAR(sb, c));
            }
        }

        float ac[4][4][4];
        #pragma unroll
        for (int i = 0; i < 4; ++i)
            #pragma unroll
            for (int j = 0; j < 4; ++j)
                #pragma unroll
                for (int k = 0; k < 4; ++k) ac[i][j][k] = 0.0f;

        int s = 0, q = 0;
        for (int c = 0; c < KCH; ++c) {
            MBARRIER_WAIT_PARITY(FULL_BAR(sb, s), (uint32_t)(q & 1));

            uint32_t Ab = sb + SMEM_T0 + s * ST_SZ;
            uint32_t Bb = Ab + A_SZ;
            #pragma unroll
            for (int ks = 0; ks < BK / 16; ++ks) {
                uint32_t af[16], bf[8];
                #pragma unroll
                for (int i = 0; i < 4; ++i) {
                    int row = wm * 64 + i * 16 + (lid & 15);
                    int chunk = ks * 2 + (lid >> 4);
                    uint32_t addr = Ab + (uint32_t)(row * 128) + (((chunk ^ (row & 7)) & 7) << 4);
                    ldsm_x4(af + i * 4, addr);
                }
                #pragma unroll
                for (int j = 0; j < 2; ++j) {
                    int row = wn * 32 + j * 16 + ((lid >> 4) << 3) + (lid & 7);
                    int chunk = ks * 2 + ((lid >> 3) & 1);
                    uint32_t addr = Bb + (uint32_t)(row * 128) + (((chunk ^ (row & 7)) & 7) << 4);
                    ldsm_x4(bf + j * 4, addr);
                }
                #pragma unroll
                for (int i = 0; i < 4; ++i) {
                    #pragma unroll
                    for (int jj = 0; jj < 4; ++jj) {
                        mma16816(ac[i][jj], &af[i * 4], &bf[(jj >> 1) * 4 + (jj & 1) * 2]);
                    }
                }
            }

            if (lid == 0) MBARRIER_ARRIVE(EMPTY_BAR(sb, s));

            if (tid == 0 && c + NST < KCH) {
                MBARRIER_WAIT_PARITY(EMPTY_BAR(sb, s), (uint32_t)(q & 1));
                int nc = c + NST;
                uint32_t stg = sb + SMEM_T0 + s * ST_SZ;
                MBARRIER_EXPECT_TX(FULL_BAR(sb, s), ST_SZ);
                bulk_g2s(stg,        gA + ((size_t)nc << 14), A_SZ, FULL_BAR(sb, s));
                bulk_g2s(stg + A_SZ, gB + ((size_t)nc << 15), B_SZ, FULL_BAR(sb, s));
            }
            ++s; if (s == NST) { s = 0; ++q; }
        }

        // epilogue: write 64x32 warp tile with bias
        const int m0 = mtile * BM, n0 = ntile * BN;
        const int mbase = m0 + wm * 64 + (lid >> 2);
        const int nbase = n0 + wn * 32 + (lid & 3) * 2;
        #pragma unroll
        for (int jj = 0; jj < 4; ++jj) {
            int n = nbase + jj * 8;
            float b0 = bias[n], b1 = bias[n + 1];
            #pragma unroll
            for (int i = 0; i < 4; ++i) {
                int m = mbase + i * 16;
                float2 v0 = make_float2(ac[i][jj][0] + b0, ac[i][jj][1] + b1);
                float2 v1 = make_float2(ac[i][jj][2] + b0, ac[i][jj][3] + b1);
                *reinterpret_cast<float2*>(&out[(size_t)m * OUT_F + n]) = v0;
                *reinterpret_cast<float2*>(&out[(size_t)(m + 8) * OUT_F + n]) = v1;
            }
        }
    }
}

// ---------------- launcher ----------------
extern "C" void kernel_launch(void* const* d_in, const int* in_sizes, int n_in,
                              void* d_out, int out_size) {
    const float* x    = (const float*)d_in[0];
    const int*   qw   = (const int*)  d_in[1];
    const float* qs   = (const float*)d_in[2];
    const float* bias = (const float*)d_in[3];
    const float* lA   = (const float*)d_in[4];
    const float* lB   = (const float*)d_in[5];
    float* out = (float*)d_out;

    cudaFuncSetAttribute(k_fused, cudaFuncAttributeMaxDynamicSharedMemorySize, FUSED_SMEM);

    k_init<<<1, 128>>>();
    k_fused<<<GRID_BLOCKS, 256, FUSED_SMEM>>>(reinterpret_cast<const float4*>(x),
                                              qw, qs, lA, lB, bias, out);
}

// round 15
// speedup vs baseline: 1.0505x; 1.0038x over previous
#include <cuda_runtime.h>
#include <cuda_fp16.h>
#include <cstdint>
#include <cstddef>

#define IN_F   4096
#define OUT_F  4096
#define MTOT   8192   // 4 * 2048

// ---------------- scratch (static device globals: allocation-free) -----------
__device__ __half g_Xh[(size_t)MTOT * IN_F];   // 64 MiB, tile-major swizzled
__device__ __half g_Wh[(size_t)OUT_F * IN_F];  // 32 MiB, tile-major swizzled
__device__ int g_cntX[64];
__device__ int g_cntW[16];
__device__ int g_tile;

// ---------------- PTX helpers ----------------
__device__ __forceinline__ uint32_t smem_u32(const void* p) {
    uint32_t r;
    asm("{ .reg .u64 t; cvta.to.shared.u64 t, %1; cvt.u32.u64 %0, t; }"
        : "=r"(r) : "l"(p));
    return r;
}
__device__ __forceinline__ void ldsm_x4(uint32_t* r, uint32_t addr) {
    asm volatile("ldmatrix.sync.aligned.m8n8.x4.shared.b16 {%0,%1,%2,%3}, [%4];"
                 : "=r"(r[0]), "=r"(r[1]), "=r"(r[2]), "=r"(r[3]) : "r"(addr));
}
__device__ __forceinline__ void mma16816(float* c, const uint32_t* a, const uint32_t* b) {
    asm volatile(
        "mma.sync.aligned.m16n8k16.row.col.f32.f16.f16.f32 "
        "{%0,%1,%2,%3}, {%4,%5,%6,%7}, {%8,%9}, {%0,%1,%2,%3};"
        : "+f"(c[0]), "+f"(c[1]), "+f"(c[2]), "+f"(c[3])
        : "r"(a[0]), "r"(a[1]), "r"(a[2]), "r"(a[3]), "r"(b[0]), "r"(b[1]));
}
__device__ __forceinline__ void bulk_g2s(uint32_t dst, const void* src, uint32_t bytes,
                                         uint32_t mbar) {
    asm volatile(
        "cp.async.bulk.shared::cta.global.mbarrier::complete_tx::bytes [%0], [%1], %2, [%3];"
        :: "r"(dst), "l"(src), "r"(bytes), "r"(mbar) : "memory");
}
__device__ __forceinline__ int ld_acq(const int* p) {
    int v;
    asm volatile("ld.acquire.gpu.s32 %0, [%1];" : "=r"(v) : "l"(p) : "memory");
    return v;
}
#define MBARRIER_INIT(addr, cnt) \
    asm volatile("mbarrier.init.shared.b64 [%0], %1;" :: "r"((uint32_t)(addr)), "r"((uint32_t)(cnt)) : "memory")
#define MBARRIER_EXPECT_TX(addr, bytes) \
    asm volatile("mbarrier.arrive.expect_tx.shared.b64 _, [%0], %1;" :: "r"((uint32_t)(addr)), "r"((uint32_t)(bytes)) : "memory")
#define MBARRIER_ARRIVE(addr) \
    asm volatile("mbarrier.arrive.release.cta.shared::cta.b64 _, [%0];" :: "r"((uint32_t)(addr)) : "memory")
#define MBARRIER_WAIT_PARITY(mbar_smem_addr, phase_parity) do {                         \
    uint32_t _mbar = (uint32_t)(mbar_smem_addr);                                        \
    uint32_t _parity = (uint32_t)(phase_parity);                                        \
    uint32_t _done;                                                                     \
    asm volatile("{\n\t.reg .pred p;\n\t"                                               \
        "mbarrier.try_wait.parity.acquire.cta.shared::cta.b64 p, [%1], %2;\n\t"         \
        "selp.b32 %0, 1, 0, p;\n\t}"                                                    \
        : "=r"(_done) : "r"(_mbar), "r"(_parity) : "memory");                           \
    if (!_done) {                                                                       \
        asm volatile("{\n\t.reg .pred P1;\n\t"                                          \
            "WAIT_LOOP_%=:\n\t"                                                         \
            "mbarrier.try_wait.parity.acquire.cta.shared::cta.b64 P1, [%0], %1, 0x989680;\n\t" \
            "@P1 bra.uni WAIT_DONE_%=;\n\t"                                             \
            "bra.uni WAIT_LOOP_%=;\n\t"                                                 \
            "WAIT_DONE_%=:\n\t}"                                                        \
            :: "r"(_mbar), "r"(_parity) : "memory");                                    \
    }                                                                                   \
} while (0)

// ---------------- config ----------------
#define TO 32
#define TI 512
#define N_FOLD_UNITS 1024          // (32 rows x 512 cols) each
#define N_CONV_UNITS 2048          // 4 x-rows each, mtile-ordered
#define CONV_SPLIT 1024            // units 0..1023 done full-width (mtiles 0..31)
#define NSTG 128                   // conv blocks (low ids) for the tail half
#define GRID_BLOCKS 296            // <= 2 * 148 SMs (all resident)

#define BM 128
#define BN 128
#define BK 64
#define NST 3
#define A_SZ (BM * 128)                   // 16384
#define B_SZ (BN * 128)                   // 16384
#define ST_SZ (A_SZ + B_SZ)               // 32768
#define SMEM_T0 1024
#define FUSED_SMEM (SMEM_T0 + NST * ST_SZ) // 99328
#define KCH (IN_F / BK)                   // 64
#define NTILES ((MTOT / BM) * (OUT_F / BN))   // 2048
#define FULL_BAR(sb, s)  ((sb) + 8 * (s))
#define EMPTY_BAR(sb, s) ((sb) + 24 + 8 * (s))

// ---------------- init kernel: zero scheduler state -------------------------
__global__ void k_init() {
    int t = threadIdx.x;
    if (t < 64) g_cntX[t] = 0;
    if (t < 16) g_cntW[t] = 0;
    if (t == 0) g_tile = 0;
}

// ---------------- staging units ----------------------------------------------
__device__ void conv_unit(int v, int tid, const float4* __restrict__ x) {
    // rows 4v .. 4v+3 of x -> g_Xh tile-major swizzled
    for (int i = tid; i < 4 * 512; i += 256) {
        int row = 4 * v + (i >> 9);
        int kg = i & 511;
        int g = row * 512 + kg;
        float4 v0 = x[g * 2], v1 = x[g * 2 + 1];
        __half2 h0 = __floats2half2_rn(v0.x, v0.y);
        __half2 h1 = __floats2half2_rn(v0.z, v0.w);
        __half2 h2 = __floats2half2_rn(v1.x, v1.y);
        __half2 h3 = __floats2half2_rn(v1.z, v1.w);
        uint4 o;
        o.x = *reinterpret_cast<uint32_t*>(&h0);
        o.y = *reinterpret_cast<uint32_t*>(&h1);
        o.z = *reinterpret_cast<uint32_t*>(&h2);
        o.w = *reinterpret_cast<uint32_t*>(&h3);
        int kchunk = kg >> 3, chunk = kg & 7;
        int r = row & 127, mtile = row >> 7;
        size_t off = ((size_t)(mtile * 64 + kchunk) << 14)
                   + (uint32_t)(r * 128 + (((chunk ^ (r & 7)) & 7) << 4));
        *reinterpret_cast<uint4*>(reinterpret_cast<char*>(g_Xh) + off) = o;
    }
}

__device__ void fold_unit(int u, int tid, char* smem,
                          const int* __restrict__ qw, const float* __restrict__ qs,
                          const float* __restrict__ A, const float* __restrict__ B) {
    float (*As)[TI + 4] = (float (*)[TI + 4])(smem + SMEM_T0);
    float (*Bs)[16]     = (float (*)[16])(smem + SMEM_T0 + 16 * (TI + 4) * 4);
    float* Ss           = (float*)(smem + SMEM_T0 + 16 * (TI + 4) * 4 + TO * 16 * 4);
    const int ob = u >> 3;               // row strip 0..127
    const int cb = (u & 7) * TI;         // col strip base
    const int o0 = ob * TO;
    for (int t = tid; t < TO * 16; t += 256)
        Bs[t / 16][t % 16] = B[(size_t)(o0 + t / 16) * 16 + (t % 16)];
    if (tid < TO) Ss[tid] = qs[o0 + tid];
    for (int t = tid; t < 16 * (TI / 4); t += 256) {
        int r = t / (TI / 4), j = t % (TI / 4);
        float4 v = reinterpret_cast<const float4*>(A + (size_t)r * IN_F + cb)[j];
        *reinterpret_cast<float4*>(&As[r][j * 4]) = v;
    }
    __syncthreads();
    const int ro = tid >> 3;    // 0..31
    const int l8 = tid & 7;     // 0..7
    const int o = o0 + ro;
    const int ntile = o >> 8, rr = o & 255;
    const float s = Ss[ro];
    const float* brow = Bs[ro];
    #pragma unroll 4
    for (int j = 0; j < TI / 32; ++j) {
        int il = l8 * 4 + j * 32;
        int4 q4 = *reinterpret_cast<const int4*>(&qw[(size_t)o * IN_F + cb + il]);
        float a0 = q4.x * s, a1 = q4.y * s, a2 = q4.z * s, a3 = q4.w * s;
        #pragma unroll
        for (int r = 0; r < 16; ++r) {
            float b2 = 2.0f * brow[r];
            a0 = fmaf(b2, As[r][il + 0], a0);
            a1 = fmaf(b2, As[r][il + 1], a1);
            a2 = fmaf(b2, As[r][il + 2], a2);
            a3 = fmaf(b2, As[r][il + 3], a3);
        }
        __half2 h0 = __floats2half2_rn(a0, a1);
        __half2 h1 = __floats2half2_rn(a2, a3);
        uint2 w;
        w.x = *reinterpret_cast<uint32_t*>(&h0);
        w.y = *reinterpret_cast<uint32_t*>(&h1);
        int col = cb + il;
        int kchunk = col >> 6;
        int c6 = col & 63;
        int chunk = c6 >> 3, within = c6 & 7;
        size_t off = ((size_t)(ntile * 64 + kchunk) << 15)
                   + (uint32_t)(rr * 128 + (((chunk ^ (rr & 7)) & 7) << 4) + within * 2);
        *reinterpret_cast<uint2*>(reinterpret_cast<char*>(g_Wh) + off) = w;
    }
}

// ---------------- fused persistent kernel ------------------------------------
__global__ void __launch_bounds__(256, 2)
k_fused(const float4* __restrict__ x,
        const int* __restrict__ qw, const float* __restrict__ qs,
        const float* __restrict__ A, const float* __restrict__ B,
        const float* __restrict__ bias, float* __restrict__ out) {
    extern __shared__ char smem[];
    uint32_t sb = smem_u32(smem);
    const int tid = threadIdx.x;
    const int bid = blockIdx.x;
    const int wid = tid >> 5, lid = tid & 31;
    const int wm = wid & 1;
    const int wn = wid >> 1;

    // -------- phase A: fold W on ALL blocks (full width) --------
    for (int u = bid; u < N_FOLD_UNITS; u += GRID_BLOCKS) {
        fold_unit(u, tid, smem, qw, qs, A, B);
        __threadfence();
        __syncthreads();
        if (tid == 0) atomicAdd(&g_cntW[u >> 6], 1);
        __syncthreads();
    }

    // -------- phase B1: conv mtiles 0..31 on ALL blocks (full width) --------
    for (int v = bid; v < CONV_SPLIT; v += GRID_BLOCKS) {
        conv_unit(v, tid, x);
        __threadfence();
        __syncthreads();
        if (tid == 0) atomicAdd(&g_cntX[v >> 5], 1);
        __syncthreads();
    }

    // -------- phase B2: conv mtiles 32..63 on blocks 0..NSTG-1 --------
    if (bid < NSTG) {
        for (int v = CONV_SPLIT + bid; v < N_CONV_UNITS; v += NSTG) {
            conv_unit(v, tid, x);
            __threadfence();
            __syncthreads();
            if (tid == 0) atomicAdd(&g_cntX[v >> 5], 1);
            __syncthreads();
        }
    }

    // -------- phase C: persistent GEMM tile loop --------
    volatile int* sm_t = (volatile int*)(smem + 64);
    for (;;) {
        if (tid == 0) *sm_t = atomicAdd(&g_tile, 1);
        __syncthreads();
        int t = *sm_t;
        if (t >= NTILES) break;
        const int mtile = t >> 5;        // mtile-major: matches conv production order
        const int ntile = t & 31;
        const char* gA = reinterpret_cast<const char*>(g_Xh) + ((size_t)mtile * 64 << 14);
        const char* gB = reinterpret_cast<const char*>(g_Wh)
                       + ((size_t)(ntile >> 1) * 64 << 15) + (size_t)(ntile & 1) * 16384;

        if (tid == 0) {
            while (ld_acq(&g_cntW[ntile >> 1]) < 64) __nanosleep(256);
            while (ld_acq(&g_cntX[mtile]) < 32)      __nanosleep(256);
            #pragma unroll
            for (int s = 0; s < NST; ++s) {
                MBARRIER_INIT(FULL_BAR(sb, s), 1);
                MBARRIER_INIT(EMPTY_BAR(sb, s), 8);
            }
        }
        __syncthreads();

        if (tid == 0) {
            #pragma unroll
            for (int c = 0; c < NST; ++c) {
                uint32_t stg = sb + SMEM_T0 + c * ST_SZ;
                MBARRIER_EXPECT_TX(FULL_BAR(sb, c), ST_SZ);
                bulk_g2s(stg,        gA + ((size_t)c << 14), A_SZ, FULL_BAR(sb, c));
                bulk_g2s(stg + A_SZ, gB + ((size_t)c << 15), B_SZ, FULL_BAR(sb, c));
            }
        }

        float ac[4][4][4];
        #pragma unroll
        for (int i = 0; i < 4; ++i)
            #pragma unroll
            for (int j = 0; j < 4; ++j)
                #pragma unroll
                for (int k = 0; k < 4; ++k) ac[i][j][k] = 0.0f;

        int s = 0, q = 0;
        for (int c = 0; c < KCH; ++c) {
            MBARRIER_WAIT_PARITY(FULL_BAR(sb, s), (uint32_t)(q & 1));

            uint32_t Ab = sb + SMEM_T0 + s * ST_SZ;
            uint32_t Bb = Ab + A_SZ;
            #pragma unroll
            for (int ks = 0; ks < BK / 16; ++ks) {
                uint32_t af[16], bf[8];
                #pragma unroll
                for (int i = 0; i < 4; ++i) {
                    int row = wm * 64 + i * 16 + (lid & 15);
                    int chunk = ks * 2 + (lid >> 4);
                    uint32_t addr = Ab + (uint32_t)(row * 128) + (((chunk ^ (row & 7)) & 7) << 4);
                    ldsm_x4(af + i * 4, addr);
                }
                #pragma unroll
                for (int j = 0; j < 2; ++j) {
                    int row = wn * 32 + j * 16 + ((lid >> 4) << 3) + (lid & 7);
                    int chunk = ks * 2 + ((lid >> 3) & 1);
                    uint32_t addr = Bb + (uint32_t)(row * 128) + (((chunk ^ (row & 7)) & 7) << 4);
                    ldsm_x4(bf + j * 4, addr);
                }
                #pragma unroll
                for (int i = 0; i < 4; ++i) {
                    #pragma unroll
                    for (int jj = 0; jj < 4; ++jj) {
                        mma16816(ac[i][jj], &af[i * 4], &bf[(jj >> 1) * 4 + (jj & 1) * 2]);
                    }
                }
            }

            if (lid == 0) MBARRIER_ARRIVE(EMPTY_BAR(sb, s));

            if (tid == 0 && c + NST < KCH) {
                MBARRIER_WAIT_PARITY(EMPTY_BAR(sb, s), (uint32_t)(q & 1));
                int nc = c + NST;
                uint32_t stg = sb + SMEM_T0 + s * ST_SZ;
                MBARRIER_EXPECT_TX(FULL_BAR(sb, s), ST_SZ);
                bulk_g2s(stg,        gA + ((size_t)nc << 14), A_SZ, FULL_BAR(sb, s));
                bulk_g2s(stg + A_SZ, gB + ((size_t)nc << 15), B_SZ, FULL_BAR(sb, s));
            }
            ++s; if (s == NST) { s = 0; ++q; }
        }

        // epilogue: write 64x32 warp tile with bias
        const int m0 = mtile * BM, n0 = ntile * BN;
        const int mbase = m0 + wm * 64 + (lid >> 2);
        const int nbase = n0 + wn * 32 + (lid & 3) * 2;
        #pragma unroll
        for (int jj = 0; jj < 4; ++jj) {
            int n = nbase + jj * 8;
            float b0 = bias[n], b1 = bias[n + 1];
            #pragma unroll
            for (int i = 0; i < 4; ++i) {
                int m = mbase + i * 16;
                float2 v0 = make_float2(ac[i][jj][0] + b0, ac[i][jj][1] + b1);
                float2 v1 = make_float2(ac[i][jj][2] + b0, ac[i][jj][3] + b1);
                *reinterpret_cast<float2*>(&out[(size_t)m * OUT_F + n]) = v0;
                *reinterpret_cast<float2*>(&out[(size_t)(m + 8) * OUT_F + n]) = v1;
            }
        }
    }
}

// ---------------- launcher ----------------
extern "C" void kernel_launch(void* const* d_in, const int* in_sizes, int n_in,
                              void* d_out, int out_size) {
    const float* x    = (const float*)d_in[0];
    const int*   qw   = (const int*)  d_in[1];
    const float* qs   = (const float*)d_in[2];
    const float* bias = (const float*)d_in[3];
    const float* lA   = (const float*)d_in[4];
    const float* lB   = (const float*)d_in[5];
    float* out = (float*)d_out;

    cudaFuncSetAttribute(k_fused, cudaFuncAttributeMaxDynamicSharedMemorySize, FUSED_SMEM);

    k_init<<<1, 128>>>();
    k_fused<<<GRID_BLOCKS, 256, FUSED_SMEM>>>(reinterpret_cast<const float4*>(x),
                                              qw, qs, lA, lB, bias, out);
}